// round 16
// baseline (speedup 1.0000x reference)
#include <cuda_runtime.h>
#include <cstddef>

#define NN 16384
#define CC 10000
#define DD 128
#define LR 0.5f

#define NVEC   (CC / 4)       // 2500 float4 per label row
#define SCANT  64             // threads per scan block (2 warps)
#define CHUNKV (SCANT * 3)    // 192 float4 = 3KB lockstep chunks (MLP=3)

// Scratch (no cudaMalloc allowed). Zero-initialized at module load; the
// finalize kernel re-zeroes after each use so every graph replay starts clean.
__device__ float g_sum[CC * DD];  // per-class sum of preds
__device__ float g_cnt[CC];      // per-class sample count

// ---------------------------------------------------------------------------
// Kernel 1: one 64-thread block per sample. Lockstep early-exit scan in 3KB
// chunks, 3 independent float4 loads in flight per thread (MLP=3). One
// __syncthreads_or per chunk gives a uniform exit predicate; s_cls is written
// at most once, always before the barrier every reader crosses.
// E[bytes/row] ~ (40KB + 3KB)/2 = 21.5KB. Labels via __ldcs (streamed once).
// After the REDs, each block fires the PDL trigger so the finalize grid can
// launch and run its scan-independent prologue under the scan's tail drain.
// ---------------------------------------------------------------------------
__global__ void __launch_bounds__(SCANT) cl_scan_accum_kernel(
    const float* __restrict__ labels,   // [N, C]
    const float* __restrict__ preds)    // [N, D]
{
    __shared__ int s_cls;
    const int n = blockIdx.x;
    const int t = threadIdx.x;

    const float4* __restrict__ row =
        reinterpret_cast<const float4*>(labels + (size_t)n * CC);

    int cls = -1;
    #pragma unroll 1
    for (int base = 0; base < NVEC; base += CHUNKV) {
        const int i0 = base + t;
        const int i1 = base + t + SCANT;
        const int i2 = base + t + 2 * SCANT;

        float4 v0, v1, v2;
        const bool p0 = (i0 < NVEC);
        const bool p1 = (i1 < NVEC);
        const bool p2 = (i2 < NVEC);
        if (p0) v0 = __ldcs(&row[i0]);    // 3 loads issued back-to-back
        if (p1) v1 = __ldcs(&row[i1]);
        if (p2) v2 = __ldcs(&row[i2]);

        int found = -1;
        if (p0) {
            if (v0.x != 0.0f)      found = 4 * i0 + 0;
            else if (v0.y != 0.0f) found = 4 * i0 + 1;
            else if (v0.z != 0.0f) found = 4 * i0 + 2;
            else if (v0.w != 0.0f) found = 4 * i0 + 3;
        }
        if (found < 0 && p1) {
            if (v1.x != 0.0f)      found = 4 * i1 + 0;
            else if (v1.y != 0.0f) found = 4 * i1 + 1;
            else if (v1.z != 0.0f) found = 4 * i1 + 2;
            else if (v1.w != 0.0f) found = 4 * i1 + 3;
        }
        if (found < 0 && p2) {
            if (v2.x != 0.0f)      found = 4 * i2 + 0;
            else if (v2.y != 0.0f) found = 4 * i2 + 1;
            else if (v2.z != 0.0f) found = 4 * i2 + 2;
            else if (v2.w != 0.0f) found = 4 * i2 + 3;
        }

        if (found >= 0) s_cls = found;        // at most one write, ever
        if (__syncthreads_or(found >= 0)) {   // uniform exit decision
            cls = s_cls;                      // write was pre-barrier: visible
            break;
        }
    }

    // Accumulate preds[n,:] into g_sum[cls,:]; 64 threads x 2 dims.
    // Return value unused -> compiles to RED (no round trip).
    const float* __restrict__ pr = preds + (size_t)n * DD;
    atomicAdd(&g_sum[(size_t)cls * DD + t],         __ldg(&pr[t]));
    atomicAdd(&g_sum[(size_t)cls * DD + t + SCANT], __ldg(&pr[t + SCANT]));
    if (t == 0) atomicAdd(&g_cnt[cls], 1.0f);

    // All of this block's REDs are issued (barrier orders them); signal the
    // dependent finalize grid. PDL's dependency resolution performs the
    // memory flush that makes the REDs visible at gridsync.
    __syncthreads();
    if (t == 0) cudaTriggerProgrammaticLaunchCompletion();
}

// ---------------------------------------------------------------------------
// Kernel 2: finalize (float4 + 2x ILP) + re-zero scratch. PDL secondary:
// launches while the scan tail drains; preloads the scan-independent center
// values BEFORE cudaGridDependencySynchronize(), hiding 5.1MB of DRAM
// traffic and the launch ramp under the scan. Post-sync work is ~15MB.
//   out[c] = (1 - LR*cnt/(cnt+1)) * center[c] + (LR/(cnt+1)) * sum[c]
// Thread handles float4 pair {2i, 2i+1} (same class; 32 float4 per class).
// A 256-thread block covers 16 whole classes -> g_cnt block-private:
// read before the barrier, zero after it.
// ---------------------------------------------------------------------------
__global__ void __launch_bounds__(256) cl_finalize_kernel(
    const float* __restrict__ center,   // [C, D]
    float* __restrict__ out)            // [C, D]
{
    const int i  = blockIdx.x * 256 + threadIdx.x;
    const int i4 = 2 * i;                       // first float4 index
    const int c  = i4 >> 5;                     // 32 float4 per class

    const float4* __restrict__ gc = reinterpret_cast<const float4*>(center);

    // Scan-independent prologue (overlapped with scan tail).
    const float4 c0 = __ldg(&gc[i4]);
    const float4 c1 = __ldg(&gc[i4 + 1]);

    cudaGridDependencySynchronize();            // scan REDs visible after this

    const float4* __restrict__ gs = reinterpret_cast<const float4*>(g_sum);
    const float cnt = __ldcg(&g_cnt[c]);
    const float4 s0 = __ldcg(&gs[i4]);
    const float4 s1 = __ldcg(&gs[i4 + 1]);

    const float inv = 1.0f / (cnt + 1.0f);
    const float a   = 1.0f - LR * cnt * inv;    // coeff on center
    const float b   = LR * inv;                 // coeff on sum

    float4 r0, r1;
    r0.x = a * c0.x + b * s0.x;  r0.y = a * c0.y + b * s0.y;
    r0.z = a * c0.z + b * s0.z;  r0.w = a * c0.w + b * s0.w;
    r1.x = a * c1.x + b * s1.x;  r1.y = a * c1.y + b * s1.y;
    r1.z = a * c1.z + b * s1.z;  r1.w = a * c1.w + b * s1.w;

    float4* __restrict__ po = reinterpret_cast<float4*>(out);
    po[i4]     = r0;
    po[i4 + 1] = r1;

    float4* gsw = reinterpret_cast<float4*>(g_sum);
    const float4 z = make_float4(0.f, 0.f, 0.f, 0.f);
    gsw[i4]     = z;                            // clean for next replay
    gsw[i4 + 1] = z;

    __syncthreads();                            // all g_cnt reads done
    if ((i & 15) == 0) {                        // one thread per class
        g_cnt[c] = 0.0f;
    }
}

// ---------------------------------------------------------------------------
// Launch. Inputs per metadata: embeded_preds [N*D], labels [N*C],
// center [C*D]. Output: updated_center [C*D] float32. Finalize launched as a
// PDL secondary (programmatic stream serialization) so its prologue overlaps
// the scan's tail; graph capture records the programmatic edge.
// ---------------------------------------------------------------------------
extern "C" void kernel_launch(void* const* d_in, const int* in_sizes, int n_in,
                              void* d_out, int out_size) {
    const float* preds  = (const float*)d_in[0];
    const float* labels = (const float*)d_in[1];
    const float* center = (const float*)d_in[2];
    float* out = (float*)d_out;

    (void)in_sizes; (void)n_in; (void)out_size;

    cl_scan_accum_kernel<<<NN, SCANT>>>(labels, preds);

    cudaLaunchConfig_t cfg = {};
    cfg.gridDim  = dim3((CC * DD / 8) / 256);   // 625 blocks
    cfg.blockDim = dim3(256);
    cfg.dynamicSmemBytes = 0;
    cfg.stream = 0;

    cudaLaunchAttribute attr[1];
    attr[0].id = cudaLaunchAttributeProgrammaticStreamSerialization;
    attr[0].val.programmaticStreamSerializationAllowed = 1;
    cfg.attrs = attr;
    cfg.numAttrs = 1;

    cudaLaunchKernelEx(&cfg, cl_finalize_kernel, center, out);
}

// round 17
// speedup vs baseline: 1.0604x; 1.0604x over previous
#include <cuda_runtime.h>
#include <cstddef>

#define NN 16384
#define CC 10000
#define DD 128
#define LR 0.5f

#define NVEC   (CC / 4)       // 2500 float4 per label row
#define SCANT  64             // threads per scan block (2 warps)
#define CHUNKV (SCANT * 3)    // 192 float4 = 3KB lockstep chunks (MLP=3)

#define FIN_F4   (CC * DD / 4)            // 320000 float4 total
#define FIN_THR  (FIN_F4 / 4)             // 80000 threads, 4 float4 each
#define FIN_GRID ((FIN_THR + 255) / 256)  // 313 blocks

// Scratch (no cudaMalloc allowed). Zero-initialized at module load; the
// finalize kernel re-zeroes after each use so every graph replay starts clean.
__device__ float g_sum[CC * DD];  // per-class sum of preds
__device__ float g_cnt[CC];      // per-class sample count

// ---------------------------------------------------------------------------
// Kernel 1 (R13, proven 60.8us @ ~5.9TB/s): one 64-thread block per sample.
// Lockstep early-exit scan in 3KB chunks, 3 independent float4 loads in
// flight per thread. One __syncthreads_or per chunk gives a uniform exit
// predicate; s_cls is written at most once, always before the barrier every
// reader crosses. E[bytes/row] ~ (40KB + 3KB)/2 = 21.5KB. Labels via __ldcs
// (streamed once, evict-first -> g_sum REDs stay L2-hot).
// ---------------------------------------------------------------------------
__global__ void __launch_bounds__(SCANT) cl_scan_accum_kernel(
    const float* __restrict__ labels,   // [N, C]
    const float* __restrict__ preds)    // [N, D]
{
    __shared__ int s_cls;
    const int n = blockIdx.x;
    const int t = threadIdx.x;

    const float4* __restrict__ row =
        reinterpret_cast<const float4*>(labels + (size_t)n * CC);

    int cls = -1;
    #pragma unroll 1
    for (int base = 0; base < NVEC; base += CHUNKV) {
        const int i0 = base + t;
        const int i1 = base + t + SCANT;
        const int i2 = base + t + 2 * SCANT;

        float4 v0, v1, v2;
        const bool p0 = (i0 < NVEC);
        const bool p1 = (i1 < NVEC);
        const bool p2 = (i2 < NVEC);
        if (p0) v0 = __ldcs(&row[i0]);    // 3 loads issued back-to-back
        if (p1) v1 = __ldcs(&row[i1]);
        if (p2) v2 = __ldcs(&row[i2]);

        int found = -1;
        if (p0) {
            if (v0.x != 0.0f)      found = 4 * i0 + 0;
            else if (v0.y != 0.0f) found = 4 * i0 + 1;
            else if (v0.z != 0.0f) found = 4 * i0 + 2;
            else if (v0.w != 0.0f) found = 4 * i0 + 3;
        }
        if (found < 0 && p1) {
            if (v1.x != 0.0f)      found = 4 * i1 + 0;
            else if (v1.y != 0.0f) found = 4 * i1 + 1;
            else if (v1.z != 0.0f) found = 4 * i1 + 2;
            else if (v1.w != 0.0f) found = 4 * i1 + 3;
        }
        if (found < 0 && p2) {
            if (v2.x != 0.0f)      found = 4 * i2 + 0;
            else if (v2.y != 0.0f) found = 4 * i2 + 1;
            else if (v2.z != 0.0f) found = 4 * i2 + 2;
            else if (v2.w != 0.0f) found = 4 * i2 + 3;
        }

        if (found >= 0) s_cls = found;        // at most one write, ever
        if (__syncthreads_or(found >= 0)) {   // uniform exit decision
            cls = s_cls;                      // write was pre-barrier: visible
            break;
        }
    }

    // Accumulate preds[n,:] into g_sum[cls,:]; 64 threads x 2 dims.
    // Return value unused -> compiles to RED (no round trip).
    const float* __restrict__ pr = preds + (size_t)n * DD;
    atomicAdd(&g_sum[(size_t)cls * DD + t],         __ldg(&pr[t]));
    atomicAdd(&g_sum[(size_t)cls * DD + t + SCANT], __ldg(&pr[t + SCANT]));
    if (t == 0) atomicAdd(&g_cnt[cls], 1.0f);
}

// ---------------------------------------------------------------------------
// Kernel 2: finalize, 4 float4 per thread (16 floats) + re-zero scratch.
//   out[c] = (1 - LR*cnt/(cnt+1)) * center[c] + (LR/(cnt+1)) * sum[c]
// Thread i handles float4 indices [4i, 4i+4); since each class spans 32
// float4 and 4i is 4-aligned, all four lie in ONE class (c = i>>3). Deep
// per-thread MLP (9 independent loads) hides DRAM/L2 latency; 313 blocks
// shorten ramp+drain vs 625. A 256-thread block covers exactly 32 whole
// classes -> g_cnt block-private: read before the barrier, zero after.
// g_sum/g_cnt reads via __ldcg (L2-coherent with the scan's REDs; the
// scratch is L2-resident so this is cheap).
// ---------------------------------------------------------------------------
__global__ void __launch_bounds__(256) cl_finalize_kernel(
    const float* __restrict__ center,   // [C, D]
    float* __restrict__ out)            // [C, D]
{
    const int i = blockIdx.x * 256 + threadIdx.x;
    if (i < FIN_THR) {
        const int i4 = 4 * i;                   // first float4 index
        const int c  = i >> 3;                  // 8 threads per class

        const float4* __restrict__ gs = reinterpret_cast<const float4*>(g_sum);
        const float4* __restrict__ gc = reinterpret_cast<const float4*>(center);

        // Issue all loads up front (MLP=9).
        const float  cnt = __ldcg(&g_cnt[c]);
        const float4 s0 = __ldcg(&gs[i4]);
        const float4 s1 = __ldcg(&gs[i4 + 1]);
        const float4 s2 = __ldcg(&gs[i4 + 2]);
        const float4 s3 = __ldcg(&gs[i4 + 3]);
        const float4 c0 = __ldg(&gc[i4]);
        const float4 c1 = __ldg(&gc[i4 + 1]);
        const float4 c2 = __ldg(&gc[i4 + 2]);
        const float4 c3 = __ldg(&gc[i4 + 3]);

        const float inv = 1.0f / (cnt + 1.0f);
        const float a   = 1.0f - LR * cnt * inv;    // coeff on center
        const float b   = LR * inv;                 // coeff on sum

        float4 r0, r1, r2, r3;
        r0.x = a * c0.x + b * s0.x;  r0.y = a * c0.y + b * s0.y;
        r0.z = a * c0.z + b * s0.z;  r0.w = a * c0.w + b * s0.w;
        r1.x = a * c1.x + b * s1.x;  r1.y = a * c1.y + b * s1.y;
        r1.z = a * c1.z + b * s1.z;  r1.w = a * c1.w + b * s1.w;
        r2.x = a * c2.x + b * s2.x;  r2.y = a * c2.y + b * s2.y;
        r2.z = a * c2.z + b * s2.z;  r2.w = a * c2.w + b * s2.w;
        r3.x = a * c3.x + b * s3.x;  r3.y = a * c3.y + b * s3.y;
        r3.z = a * c3.z + b * s3.z;  r3.w = a * c3.w + b * s3.w;

        float4* __restrict__ po = reinterpret_cast<float4*>(out);
        po[i4]     = r0;
        po[i4 + 1] = r1;
        po[i4 + 2] = r2;
        po[i4 + 3] = r3;

        float4* gsw = reinterpret_cast<float4*>(g_sum);
        const float4 z = make_float4(0.f, 0.f, 0.f, 0.f);
        gsw[i4]     = z;                        // clean for next replay
        gsw[i4 + 1] = z;
        gsw[i4 + 2] = z;
        gsw[i4 + 3] = z;

        __syncthreads();                        // all g_cnt reads done
        if ((i & 7) == 0) {                     // one thread per class
            g_cnt[c] = 0.0f;
        }
    } else {
        __syncthreads();                        // keep barrier uniform
    }
}

// ---------------------------------------------------------------------------
// Launch. Inputs per metadata: embeded_preds [N*D], labels [N*C],
// center [C*D]. Output: updated_center [C*D] float32. Plain sequential
// launches: PDL/fusion measured as regressions on this workload.
// ---------------------------------------------------------------------------
extern "C" void kernel_launch(void* const* d_in, const int* in_sizes, int n_in,
                              void* d_out, int out_size) {
    const float* preds  = (const float*)d_in[0];
    const float* labels = (const float*)d_in[1];
    const float* center = (const float*)d_in[2];
    float* out = (float*)d_out;

    (void)in_sizes; (void)n_in; (void)out_size;

    cl_scan_accum_kernel<<<NN, SCANT>>>(labels, preds);
    cl_finalize_kernel<<<FIN_GRID, 256>>>(center, out);
}